// round 1
// baseline (speedup 1.0000x reference)
#include <cuda_runtime.h>
#include <math.h>

#define S1 589824   // 768*768
#define S2 147456   // 384*384
#define S3 36864    // 192*192
#define NPOS 9216   // 96*96

// Scratch (device globals: no runtime allocation)
__device__ float  g_f1[16 * S1];
__device__ float  g_f2[32 * S2];
__device__ float  g_f3[64 * S3];
__device__ double2 g_part[1024];
__device__ float  g_mean[3][64];
__device__ float  g_rstd[3][64];
__device__ float  g_heads[6][NPOS];  // psi, theta, shift_c0, shift_c1, scale, tilt
__device__ float  g_tr[NPOS * 6];

// ---------------- conv1: 1 -> 16, 3x3, stride 1, pad 1, raw output ----------------
__global__ void k_conv1(const float* __restrict__ img, const float* __restrict__ w) {
    __shared__ float sw[144];
    int tid = threadIdx.y * 32 + threadIdx.x;
    if (tid < 144) sw[tid] = w[tid];
    __syncthreads();
    int x = blockIdx.x * 32 + threadIdx.x;
    int y = blockIdx.y * 8 + threadIdx.y;
    float v[9];
#pragma unroll
    for (int dy = 0; dy < 3; dy++)
#pragma unroll
        for (int dx = 0; dx < 3; dx++) {
            int yy = y + dy - 1, xx = x + dx - 1;
            v[dy * 3 + dx] = (yy >= 0 && yy < 768 && xx >= 0 && xx < 768) ? img[yy * 768 + xx] : 0.f;
        }
#pragma unroll
    for (int oc = 0; oc < 16; oc++) {
        float a = 0.f;
#pragma unroll
        for (int k = 0; k < 9; k++) a += v[k] * sw[oc * 9 + k];
        g_f1[oc * S1 + y * 768 + x] = a;
    }
}

// ---------------- deterministic per-channel mean/var reduction ----------------
__global__ void k_redp(int stage, int P, int elems) {
    const float* src = (stage == 0) ? g_f1 : ((stage == 1) ? g_f2 : g_f3);
    int ch = blockIdx.x / P, p = blockIdx.x % P;
    int chunk = elems / P;
    const float* b = src + (size_t)ch * elems + (size_t)p * chunk;
    double s = 0.0, q = 0.0;
    for (int i = threadIdx.x; i < chunk; i += 256) {
        float v = b[i];
        s += (double)v;
        q += (double)v * (double)v;
    }
    __shared__ double ss[256], sq[256];
    ss[threadIdx.x] = s; sq[threadIdx.x] = q;
    __syncthreads();
    for (int o = 128; o > 0; o >>= 1) {
        if (threadIdx.x < o) {
            ss[threadIdx.x] += ss[threadIdx.x + o];
            sq[threadIdx.x] += sq[threadIdx.x + o];
        }
        __syncthreads();
    }
    if (threadIdx.x == 0) { g_part[blockIdx.x].x = ss[0]; g_part[blockIdx.x].y = sq[0]; }
}

__global__ void k_redf(int stage, int C, int P, int elems) {
    int c = threadIdx.x;
    if (c >= C) return;
    double s = 0.0, q = 0.0;
    for (int p = 0; p < P; p++) { s += g_part[c * P + p].x; q += g_part[c * P + p].y; }
    double m = s / (double)elems;
    double var = q / (double)elems - m * m;
    g_mean[stage][c] = (float)m;
    g_rstd[stage][c] = (float)(1.0 / sqrt(var + 1e-5));
}

// ---------------- conv2: 16 -> 32, 3x3, stride 2, pad 1, bn_relu fused on input ----------------
__global__ void k_conv2(const float* __restrict__ w) {
    __shared__ float sIn[17 * 33];
    __shared__ float sW[288];
    int tid = threadIdx.y * 16 + threadIdx.x;
    int ox0 = blockIdx.x * 16, oy0 = blockIdx.y * 8;
    float acc[32];
#pragma unroll
    for (int i = 0; i < 32; i++) acc[i] = 0.f;
    int ix0 = 2 * ox0 - 1, iy0 = 2 * oy0 - 1;
    for (int ic = 0; ic < 16; ic++) {
        for (int i = tid; i < 288; i += 128) {
            int oc = i / 9, k = i % 9;
            sW[i] = w[(oc * 16 + ic) * 9 + k];
        }
        float m = g_mean[0][ic], rs = g_rstd[0][ic];
        const float* src = g_f1 + (size_t)ic * S1;
        for (int i = tid; i < 17 * 33; i += 128) {
            int r = i / 33, c = i % 33;
            int gy = iy0 + r, gx = ix0 + c;
            float v = 0.f;
            if (gy >= 0 && gy < 768 && gx >= 0 && gx < 768) {
                v = (src[gy * 768 + gx] - m) * rs;
                v = v > 0.f ? v : 0.f;
            }
            sIn[i] = v;
        }
        __syncthreads();
        float v[9];
        int r0 = 2 * threadIdx.y, c0 = 2 * threadIdx.x;
#pragma unroll
        for (int ky = 0; ky < 3; ky++)
#pragma unroll
            for (int kx = 0; kx < 3; kx++) v[ky * 3 + kx] = sIn[(r0 + ky) * 33 + c0 + kx];
#pragma unroll
        for (int oc = 0; oc < 32; oc++) {
            float a = acc[oc];
#pragma unroll
            for (int k = 0; k < 9; k++) a += v[k] * sW[oc * 9 + k];
            acc[oc] = a;
        }
        __syncthreads();
    }
    int oy = oy0 + threadIdx.y, ox = ox0 + threadIdx.x;
#pragma unroll
    for (int oc = 0; oc < 32; oc++) g_f2[oc * S2 + oy * 384 + ox] = acc[oc];
}

// ---------------- conv3: 32 -> 64, 3x3, stride 2, pad 1 ----------------
__global__ void __launch_bounds__(128) k_conv3(const float* __restrict__ w) {
    __shared__ float sIn[17 * 33];
    __shared__ float sW[576];
    int tid = threadIdx.y * 16 + threadIdx.x;
    int ox0 = blockIdx.x * 16, oy0 = blockIdx.y * 8;
    float acc[64];
#pragma unroll
    for (int i = 0; i < 64; i++) acc[i] = 0.f;
    int ix0 = 2 * ox0 - 1, iy0 = 2 * oy0 - 1;
    for (int ic = 0; ic < 32; ic++) {
        for (int i = tid; i < 576; i += 128) {
            int oc = i / 9, k = i % 9;
            sW[i] = w[(oc * 32 + ic) * 9 + k];
        }
        float m = g_mean[1][ic], rs = g_rstd[1][ic];
        const float* src = g_f2 + (size_t)ic * S2;
        for (int i = tid; i < 17 * 33; i += 128) {
            int r = i / 33, c = i % 33;
            int gy = iy0 + r, gx = ix0 + c;
            float v = 0.f;
            if (gy >= 0 && gy < 384 && gx >= 0 && gx < 384) {
                v = (src[gy * 384 + gx] - m) * rs;
                v = v > 0.f ? v : 0.f;
            }
            sIn[i] = v;
        }
        __syncthreads();
        float v[9];
        int r0 = 2 * threadIdx.y, c0 = 2 * threadIdx.x;
#pragma unroll
        for (int ky = 0; ky < 3; ky++)
#pragma unroll
            for (int kx = 0; kx < 3; kx++) v[ky * 3 + kx] = sIn[(r0 + ky) * 33 + c0 + kx];
#pragma unroll
        for (int oc = 0; oc < 64; oc++) {
            float a = acc[oc];
#pragma unroll
            for (int k = 0; k < 9; k++) a += v[k] * sW[oc * 9 + k];
            acc[oc] = a;
        }
        __syncthreads();
    }
    int oy = oy0 + threadIdx.y, ox = ox0 + threadIdx.x;
#pragma unroll
    for (int oc = 0; oc < 64; oc++) g_f3[oc * S3 + oy * 192 + ox] = acc[oc];
}

// ---------------- heads: 6 channels of 2x2/s2 conv + tanh activations ----------------
__global__ void k_heads(const float* __restrict__ pw, const float* __restrict__ pb,
                        const float* __restrict__ tw, const float* __restrict__ tb,
                        const float* __restrict__ shw, const float* __restrict__ shb,
                        const float* __restrict__ scw, const float* __restrict__ scb,
                        const float* __restrict__ tiw, const float* __restrict__ tib) {
    __shared__ float sw[1536];
    __shared__ float sb[6];
    int tid = threadIdx.x;
    for (int i = tid; i < 1536; i += 128) {
        int h = i / 256, r = i % 256;
        const float* s; int off = r;
        if (h == 0) s = pw;
        else if (h == 1) s = tw;
        else if (h == 2) s = shw;
        else if (h == 3) { s = shw; off = r + 256; }
        else if (h == 4) s = scw;
        else s = tiw;
        sw[i] = s[off];
    }
    if (tid == 0) { sb[0] = pb[0]; sb[1] = tb[0]; sb[2] = shb[0]; sb[3] = shb[1]; sb[4] = scb[0]; sb[5] = tib[0]; }
    __syncthreads();
    int n = blockIdx.x * 128 + tid;
    int y = n / 96, x = n % 96;
    float acc[6] = {0.f, 0.f, 0.f, 0.f, 0.f, 0.f};
    for (int ic = 0; ic < 64; ic++) {
        float m = g_mean[2][ic], rs = g_rstd[2][ic];
        int base = ic * S3 + (2 * y) * 192 + 2 * x;
        float v0 = (g_f3[base] - m) * rs;       v0 = v0 > 0.f ? v0 : 0.f;
        float v1 = (g_f3[base + 1] - m) * rs;   v1 = v1 > 0.f ? v1 : 0.f;
        float v2 = (g_f3[base + 192] - m) * rs; v2 = v2 > 0.f ? v2 : 0.f;
        float v3 = (g_f3[base + 193] - m) * rs; v3 = v3 > 0.f ? v3 : 0.f;
#pragma unroll
        for (int h = 0; h < 6; h++) {
            const float* ww = &sw[h * 256 + ic * 4];
            acc[h] += v0 * ww[0] + v1 * ww[1] + v2 * ww[2] + v3 * ww[3];
        }
    }
    g_heads[0][n] = 3.14159f * tanhf(acc[0] + sb[0]);
    g_heads[1][n] = 3.14159f * tanhf(acc[1] + sb[1]);
    g_heads[2][n] = 0.2f * tanhf(acc[2] + sb[2]);
    g_heads[3][n] = 0.2f * tanhf(acc[3] + sb[3]);
    float sc = 1.f + 0.25f * tanhf(acc[4] + sb[4]);
    g_heads[4][n] = fminf(fmaxf(sc, 0.8f), 1.25f);
    float ti = 1.f + 0.8f * tanhf(acc[5] + sb[5]);
    g_heads[5][n] = fminf(fmaxf(ti, 1.0f), 1.8f);
}

// ---------------- transform build + aff output ----------------
__global__ void k_transform(float* __restrict__ aff) {
    int n = blockIdx.x * 256 + threadIdx.x;
    if (n >= NPOS) return;
    float psi = g_heads[0][n], th = g_heads[1][n];
    // shift.reshape(-1,2,1) quirk: flat [c][y][x] order, pair (2n, 2n+1)
    const float* sf = &g_heads[2][0];
    float sx = sf[2 * n], sy = sf[2 * n + 1];
    float s = g_heads[4][n], t = g_heads[5][n];
    float cp = cosf(psi), sp = sinf(psi), ct = cosf(th), st = sinf(th);
    float a = t * ct, b = -t * st, c = st / t, d = ct / t;
    float A00 = s * (cp * a - sp * c), A01 = s * (cp * b - sp * d);
    float A10 = s * (sp * a + cp * c), A11 = s * (sp * b + cp * d);
    float* tr = &g_tr[n * 6];
    tr[0] = A00; tr[1] = A01; tr[2] = sx; tr[3] = A10; tr[4] = A11; tr[5] = sy;
    float* af = aff + (size_t)n * 6;
    af[0] = 32.f * A00; af[1] = 32.f * A01; af[2] = (float)(4 + 8 * (n % 96)) + 32.f * sx;
    af[3] = 32.f * A10; af[4] = 32.f * A11; af[5] = (float)(4 + 8 * (n / 96)) + 32.f * sy;
}

// ---------------- bilinear sampler ----------------
__device__ __forceinline__ float samp(const float* __restrict__ img, int py, int px, int yy, int xx) {
    if ((unsigned)xx >= 144u || (unsigned)yy >= 144u) return 0.f;
    int r = py * 8 + yy - 68, c = px * 8 + xx - 68;
    if ((unsigned)r >= 768u || (unsigned)c >= 768u) return 0.f;
    return img[r * 768 + c];
}

__global__ void k_sample(const float* __restrict__ img, float* __restrict__ outp) {
    int n = blockIdx.x;
    __shared__ float tr[6];
    if (threadIdx.x < 6) tr[threadIdx.x] = g_tr[n * 6 + threadIdx.x];
    __syncthreads();
    int px = n % 96, py = n / 96;
#pragma unroll
    for (int j = 0; j < 4; j++) {
        int idx = threadIdx.x + j * 256;
        int h = idx >> 5, w = idx & 31;
        float X = (w + 0.5f) * 0.0625f - 1.f;
        float Y = (h + 0.5f) * 0.0625f - 1.f;
        float gx = (tr[0] * X + tr[1] * Y + tr[2]) / 4.5f;
        float gy = (tr[3] * X + tr[4] * Y + tr[5]) / 4.5f;
        float ix = gx * 72.f + 71.5f;
        float iy = gy * 72.f + 71.5f;
        float x0 = floorf(ix), y0 = floorf(iy);
        float wx = ix - x0, wy = iy - y0;
        int xi = (int)x0, yi = (int)y0;
        float v00 = samp(img, py, px, yi, xi);
        float v01 = samp(img, py, px, yi, xi + 1);
        float v10 = samp(img, py, px, yi + 1, xi);
        float v11 = samp(img, py, px, yi + 1, xi + 1);
        float o = (1.f - wy) * ((1.f - wx) * v00 + wx * v01) + wy * ((1.f - wx) * v10 + wx * v11);
        outp[(size_t)n * 1024 + idx] = o;
    }
}

extern "C" void kernel_launch(void* const* d_in, const int* in_sizes, int n_in,
                              void* d_out, int out_size) {
    const float* img = (const float*)d_in[0];
    const float* w1 = (const float*)d_in[1];
    const float* w2 = (const float*)d_in[2];
    const float* w3 = (const float*)d_in[3];
    const float* pw = (const float*)d_in[4];  const float* pb = (const float*)d_in[5];
    const float* tw = (const float*)d_in[6];  const float* tb = (const float*)d_in[7];
    const float* shw = (const float*)d_in[8]; const float* shb = (const float*)d_in[9];
    const float* scw = (const float*)d_in[10]; const float* scb = (const float*)d_in[11];
    const float* tiw = (const float*)d_in[12]; const float* tib = (const float*)d_in[13];

    float* out = (float*)d_out;          // transformed: 9216*1*32*32 floats
    float* aff = out + 9216 * 1024;      // aff: 9216*2*3 floats

    k_conv1<<<dim3(24, 96), dim3(32, 8)>>>(img, w1);
    k_redp<<<16 * 64, 256>>>(0, 64, S1);
    k_redf<<<1, 64>>>(0, 16, 64, S1);
    k_conv2<<<dim3(24, 48), dim3(16, 8)>>>(w2);
    k_redp<<<32 * 32, 256>>>(1, 32, S2);
    k_redf<<<1, 64>>>(1, 32, 32, S2);
    k_conv3<<<dim3(12, 24), dim3(16, 8)>>>(w3);
    k_redp<<<64 * 16, 256>>>(2, 16, S3);
    k_redf<<<1, 64>>>(2, 64, 16, S3);
    k_heads<<<72, 128>>>(pw, pb, tw, tb, shw, shb, scw, scb, tiw, tib);
    k_transform<<<36, 256>>>(aff);
    k_sample<<<NPOS, 256>>>(img, out);
}

// round 2
// speedup vs baseline: 1.1529x; 1.1529x over previous
#include <cuda_runtime.h>
#include <math.h>

#define S1 589824   // 768*768
#define S2 147456   // 384*384
#define S3 36864    // 192*192
#define NPOS 9216   // 96*96

// Scratch (device globals: no runtime allocation)
__device__ float  g_f1[16 * S1];
__device__ float  g_f2[32 * S2];
__device__ float  g_f3[64 * S3];
__device__ double2 g_part[1024];
__device__ float  g_mean[3][64];
__device__ float  g_rstd[3][64];
__device__ float  g_heads[6][NPOS];  // psi, theta, shift_c0, shift_c1, scale, tilt
__device__ float  g_tr[NPOS * 6];

// ---------------- conv1: 1 -> 16, 3x3, stride 1, pad 1, raw output ----------------
// 4 px (x) * 16 oc per thread, weights via LDS.128 broadcast, STG.128 stores
__global__ void __launch_bounds__(128) k_conv1(const float* __restrict__ img, const float* __restrict__ w) {
    __shared__ float sw[16 * 12];
    int tid = threadIdx.x;
    for (int i = tid; i < 192; i += 128) { int oc = i / 12, k = i % 12; sw[i] = (k < 9) ? w[oc * 9 + k] : 0.f; }
    __syncthreads();
    int xg = tid & 31, y = tid >> 5;
    int x0 = blockIdx.x * 128 + 4 * xg;
    int yy = blockIdx.y * 4 + y;
    float vin[3][6];
#pragma unroll
    for (int ky = 0; ky < 3; ky++) {
        int gy = yy + ky - 1;
        if (gy >= 0 && gy < 768) {
            float4 a = *(const float4*)&img[gy * 768 + x0];
            vin[ky][1] = a.x; vin[ky][2] = a.y; vin[ky][3] = a.z; vin[ky][4] = a.w;
            vin[ky][0] = (x0 - 1 >= 0) ? img[gy * 768 + x0 - 1] : 0.f;
            vin[ky][5] = (x0 + 4 < 768) ? img[gy * 768 + x0 + 4] : 0.f;
        } else {
#pragma unroll
            for (int c = 0; c < 6; c++) vin[ky][c] = 0.f;
        }
    }
    float acc[64];
#pragma unroll
    for (int oc = 0; oc < 16; oc++) {
        const float* wp = &sw[oc * 12];
        float4 wa = *(const float4*)wp;
        float4 wb = *(const float4*)(wp + 4);
        float  w8 = wp[8];
#pragma unroll
        for (int px = 0; px < 4; px++) {
            acc[oc * 4 + px] =
                  vin[0][px] * wa.x + vin[0][px + 1] * wa.y + vin[0][px + 2] * wa.z
                + vin[1][px] * wa.w + vin[1][px + 1] * wb.x + vin[1][px + 2] * wb.y
                + vin[2][px] * wb.z + vin[2][px + 1] * wb.w + vin[2][px + 2] * w8;
        }
    }
#pragma unroll
    for (int oc = 0; oc < 16; oc++) {
        float4 o = make_float4(acc[oc * 4], acc[oc * 4 + 1], acc[oc * 4 + 2], acc[oc * 4 + 3]);
        *(float4*)&g_f1[oc * S1 + yy * 768 + x0] = o;
    }
}

// ---------------- deterministic per-channel mean/var reduction ----------------
__global__ void k_redp(int stage, int P, int elems) {
    const float* src = (stage == 0) ? g_f1 : ((stage == 1) ? g_f2 : g_f3);
    int ch = blockIdx.x / P, p = blockIdx.x % P;
    int chunk = elems / P;
    const float* b = src + (size_t)ch * elems + (size_t)p * chunk;
    double s = 0.0, q = 0.0;
    for (int i = threadIdx.x; i < chunk; i += 256) {
        float v = b[i];
        s += (double)v;
        q += (double)v * (double)v;
    }
    __shared__ double ss[256], sq[256];
    ss[threadIdx.x] = s; sq[threadIdx.x] = q;
    __syncthreads();
    for (int o = 128; o > 0; o >>= 1) {
        if (threadIdx.x < o) {
            ss[threadIdx.x] += ss[threadIdx.x + o];
            sq[threadIdx.x] += sq[threadIdx.x + o];
        }
        __syncthreads();
    }
    if (threadIdx.x == 0) { g_part[blockIdx.x].x = ss[0]; g_part[blockIdx.x].y = sq[0]; }
}

__global__ void k_redf(int stage, int C, int P, int elems) {
    int c = threadIdx.x;
    if (c >= C) return;
    double s = 0.0, q = 0.0;
    for (int p = 0; p < P; p++) { s += g_part[c * P + p].x; q += g_part[c * P + p].y; }
    double m = s / (double)elems;
    double var = q / (double)elems - m * m;
    g_mean[stage][c] = (float)m;
    g_rstd[stage][c] = (float)(1.0 / sqrt(var + 1e-5));
}

// ---------------- conv2: 16 -> 32, 3x3, stride 2, pad 1, bn_relu fused on input --------
// block: 128 thr = xg(8) x y(8) x ocg(2); tile 32x8 out px; thread: 4px x 16oc
__global__ void __launch_bounds__(128) k_conv2(const float* __restrict__ w) {
    __shared__ float sIn[17 * 68];
    __shared__ float sW[16 * 32 * 12];   // [ic][oc][12]
    int tid = threadIdx.x;
    for (int i = tid; i < 16 * 32 * 12; i += 128) {
        int ic = i / 384; int r = i % 384; int oc = r / 12, k = r % 12;
        sW[i] = (k < 9) ? w[(oc * 16 + ic) * 9 + k] : 0.f;
    }
    int xg = tid & 7, y = (tid >> 3) & 7, ocg = tid >> 6;
    int ox0 = blockIdx.x * 32, oy0 = blockIdx.y * 8;
    int ix0 = 2 * ox0 - 1, iy0 = 2 * oy0 - 1;
    float acc[64];
#pragma unroll
    for (int i = 0; i < 64; i++) acc[i] = 0.f;
#pragma unroll 1
    for (int ic = 0; ic < 16; ic++) {
        float m = g_mean[0][ic], rs = g_rstd[0][ic];
        const float* src = g_f1 + (size_t)ic * S1;
        for (int i = tid; i < 17 * 65; i += 128) {
            int r = i / 65, c = i % 65;
            int gy = iy0 + r, gx = ix0 + c;
            float v = 0.f;
            if (gy >= 0 && gy < 768 && gx >= 0 && gx < 768) {
                v = (src[gy * 768 + gx] - m) * rs;
                v = v > 0.f ? v : 0.f;
            }
            sIn[r * 68 + c] = v;
        }
        __syncthreads();
        float vin[3][9];
        int r0 = 2 * y, c0 = 8 * xg;
#pragma unroll
        for (int ky = 0; ky < 3; ky++) {
            const float* row = &sIn[(r0 + ky) * 68 + c0];
            float4 a = *(const float4*)row;
            float4 b = *(const float4*)(row + 4);
            vin[ky][0] = a.x; vin[ky][1] = a.y; vin[ky][2] = a.z; vin[ky][3] = a.w;
            vin[ky][4] = b.x; vin[ky][5] = b.y; vin[ky][6] = b.z; vin[ky][7] = b.w;
            vin[ky][8] = row[8];
        }
#pragma unroll
        for (int oc = 0; oc < 16; oc++) {
            const float* wp = &sW[ic * 384 + (ocg * 16 + oc) * 12];
            float4 wa = *(const float4*)wp;
            float4 wb = *(const float4*)(wp + 4);
            float  w8 = wp[8];
#pragma unroll
            for (int px = 0; px < 4; px++) {
                acc[oc * 4 + px] +=
                      vin[0][2 * px] * wa.x + vin[0][2 * px + 1] * wa.y + vin[0][2 * px + 2] * wa.z
                    + vin[1][2 * px] * wa.w + vin[1][2 * px + 1] * wb.x + vin[1][2 * px + 2] * wb.y
                    + vin[2][2 * px] * wb.z + vin[2][2 * px + 1] * wb.w + vin[2][2 * px + 2] * w8;
            }
        }
        __syncthreads();
    }
    int oy = oy0 + y, oxb = ox0 + 4 * xg;
#pragma unroll
    for (int oc = 0; oc < 16; oc++) {
        float4 o = make_float4(acc[oc * 4], acc[oc * 4 + 1], acc[oc * 4 + 2], acc[oc * 4 + 3]);
        *(float4*)&g_f2[(ocg * 16 + oc) * S2 + oy * 384 + oxb] = o;
    }
}

// ---------------- conv3: 32 -> 64, 3x3, stride 2, pad 1 ----------------
// block: 128 thr = xg(4) x y(8) x ocg(4); tile 16x8 out px; thread: 4px x 16oc
__global__ void __launch_bounds__(128) k_conv3(const float* __restrict__ w) {
    __shared__ float sIn[17 * 36];
    __shared__ float sW[64 * 12];   // per-ic [oc][12]
    int tid = threadIdx.x;
    int xg = tid & 3, y = (tid >> 2) & 7, ocg = tid >> 5;
    int ox0 = blockIdx.x * 16, oy0 = blockIdx.y * 8;
    int ix0 = 2 * ox0 - 1, iy0 = 2 * oy0 - 1;
    float acc[64];
#pragma unroll
    for (int i = 0; i < 64; i++) acc[i] = 0.f;
#pragma unroll 1
    for (int ic = 0; ic < 32; ic++) {
        for (int i = tid; i < 64 * 12; i += 128) {
            int oc = i / 12, k = i % 12;
            sW[i] = (k < 9) ? w[(oc * 32 + ic) * 9 + k] : 0.f;
        }
        float m = g_mean[1][ic], rs = g_rstd[1][ic];
        const float* src = g_f2 + (size_t)ic * S2;
        for (int i = tid; i < 17 * 33; i += 128) {
            int r = i / 33, c = i % 33;
            int gy = iy0 + r, gx = ix0 + c;
            float v = 0.f;
            if (gy >= 0 && gy < 384 && gx >= 0 && gx < 384) {
                v = (src[gy * 384 + gx] - m) * rs;
                v = v > 0.f ? v : 0.f;
            }
            sIn[r * 36 + c] = v;
        }
        __syncthreads();
        float vin[3][9];
        int r0 = 2 * y, c0 = 8 * xg;
#pragma unroll
        for (int ky = 0; ky < 3; ky++) {
            const float* row = &sIn[(r0 + ky) * 36 + c0];
            float4 a = *(const float4*)row;
            float4 b = *(const float4*)(row + 4);
            vin[ky][0] = a.x; vin[ky][1] = a.y; vin[ky][2] = a.z; vin[ky][3] = a.w;
            vin[ky][4] = b.x; vin[ky][5] = b.y; vin[ky][6] = b.z; vin[ky][7] = b.w;
            vin[ky][8] = row[8];
        }
#pragma unroll
        for (int oc = 0; oc < 16; oc++) {
            const float* wp = &sW[(ocg * 16 + oc) * 12];
            float4 wa = *(const float4*)wp;
            float4 wb = *(const float4*)(wp + 4);
            float  w8 = wp[8];
#pragma unroll
            for (int px = 0; px < 4; px++) {
                acc[oc * 4 + px] +=
                      vin[0][2 * px] * wa.x + vin[0][2 * px + 1] * wa.y + vin[0][2 * px + 2] * wa.z
                    + vin[1][2 * px] * wa.w + vin[1][2 * px + 1] * wb.x + vin[1][2 * px + 2] * wb.y
                    + vin[2][2 * px] * wb.z + vin[2][2 * px + 1] * wb.w + vin[2][2 * px + 2] * w8;
            }
        }
        __syncthreads();
    }
    int oy = oy0 + y, oxb = ox0 + 4 * xg;
#pragma unroll
    for (int oc = 0; oc < 16; oc++) {
        float4 o = make_float4(acc[oc * 4], acc[oc * 4 + 1], acc[oc * 4 + 2], acc[oc * 4 + 3]);
        *(float4*)&g_f3[(ocg * 16 + oc) * S3 + oy * 192 + oxb] = o;
    }
}

// ---------------- heads: 6 channels of 2x2/s2 conv + tanh activations ----------------
__global__ void k_heads(const float* __restrict__ pw, const float* __restrict__ pb,
                        const float* __restrict__ tw, const float* __restrict__ tb,
                        const float* __restrict__ shw, const float* __restrict__ shb,
                        const float* __restrict__ scw, const float* __restrict__ scb,
                        const float* __restrict__ tiw, const float* __restrict__ tib) {
    __shared__ float sw[1536];
    __shared__ float sb[6];
    int tid = threadIdx.x;
    for (int i = tid; i < 1536; i += 128) {
        int h = i / 256, r = i % 256;
        const float* s; int off = r;
        if (h == 0) s = pw;
        else if (h == 1) s = tw;
        else if (h == 2) s = shw;
        else if (h == 3) { s = shw; off = r + 256; }
        else if (h == 4) s = scw;
        else s = tiw;
        sw[i] = s[off];
    }
    if (tid == 0) { sb[0] = pb[0]; sb[1] = tb[0]; sb[2] = shb[0]; sb[3] = shb[1]; sb[4] = scb[0]; sb[5] = tib[0]; }
    __syncthreads();
    int n = blockIdx.x * 128 + tid;
    int y = n / 96, x = n % 96;
    float acc[6] = {0.f, 0.f, 0.f, 0.f, 0.f, 0.f};
    for (int ic = 0; ic < 64; ic++) {
        float m = g_mean[2][ic], rs = g_rstd[2][ic];
        int base = ic * S3 + (2 * y) * 192 + 2 * x;
        float v0 = (g_f3[base] - m) * rs;       v0 = v0 > 0.f ? v0 : 0.f;
        float v1 = (g_f3[base + 1] - m) * rs;   v1 = v1 > 0.f ? v1 : 0.f;
        float v2 = (g_f3[base + 192] - m) * rs; v2 = v2 > 0.f ? v2 : 0.f;
        float v3 = (g_f3[base + 193] - m) * rs; v3 = v3 > 0.f ? v3 : 0.f;
#pragma unroll
        for (int h = 0; h < 6; h++) {
            const float* ww = &sw[h * 256 + ic * 4];
            acc[h] += v0 * ww[0] + v1 * ww[1] + v2 * ww[2] + v3 * ww[3];
        }
    }
    g_heads[0][n] = 3.14159f * tanhf(acc[0] + sb[0]);
    g_heads[1][n] = 3.14159f * tanhf(acc[1] + sb[1]);
    g_heads[2][n] = 0.2f * tanhf(acc[2] + sb[2]);
    g_heads[3][n] = 0.2f * tanhf(acc[3] + sb[3]);
    float sc = 1.f + 0.25f * tanhf(acc[4] + sb[4]);
    g_heads[4][n] = fminf(fmaxf(sc, 0.8f), 1.25f);
    float ti = 1.f + 0.8f * tanhf(acc[5] + sb[5]);
    g_heads[5][n] = fminf(fmaxf(ti, 1.0f), 1.8f);
}

// ---------------- transform build + aff output ----------------
__global__ void k_transform(float* __restrict__ aff) {
    int n = blockIdx.x * 256 + threadIdx.x;
    if (n >= NPOS) return;
    float psi = g_heads[0][n], th = g_heads[1][n];
    const float* sf = &g_heads[2][0];
    float sx = sf[2 * n], sy = sf[2 * n + 1];
    float s = g_heads[4][n], t = g_heads[5][n];
    float cp = cosf(psi), sp = sinf(psi), ct = cosf(th), st = sinf(th);
    float a = t * ct, b = -t * st, c = st / t, d = ct / t;
    float A00 = s * (cp * a - sp * c), A01 = s * (cp * b - sp * d);
    float A10 = s * (sp * a + cp * c), A11 = s * (sp * b + cp * d);
    float* tr = &g_tr[n * 6];
    tr[0] = A00; tr[1] = A01; tr[2] = sx; tr[3] = A10; tr[4] = A11; tr[5] = sy;
    float* af = aff + (size_t)n * 6;
    af[0] = 32.f * A00; af[1] = 32.f * A01; af[2] = (float)(4 + 8 * (n % 96)) + 32.f * sx;
    af[3] = 32.f * A10; af[4] = 32.f * A11; af[5] = (float)(4 + 8 * (n / 96)) + 32.f * sy;
}

// ---------------- bilinear sampler ----------------
__device__ __forceinline__ float samp(const float* __restrict__ img, int py, int px, int yy, int xx) {
    if ((unsigned)xx >= 144u || (unsigned)yy >= 144u) return 0.f;
    int r = py * 8 + yy - 68, c = px * 8 + xx - 68;
    if ((unsigned)r >= 768u || (unsigned)c >= 768u) return 0.f;
    return img[r * 768 + c];
}

__global__ void k_sample(const float* __restrict__ img, float* __restrict__ outp) {
    int n = blockIdx.x;
    __shared__ float tr[6];
    if (threadIdx.x < 6) tr[threadIdx.x] = g_tr[n * 6 + threadIdx.x];
    __syncthreads();
    int px = n % 96, py = n / 96;
#pragma unroll
    for (int j = 0; j < 4; j++) {
        int idx = threadIdx.x + j * 256;
        int h = idx >> 5, w = idx & 31;
        float X = (w + 0.5f) * 0.0625f - 1.f;
        float Y = (h + 0.5f) * 0.0625f - 1.f;
        float gx = (tr[0] * X + tr[1] * Y + tr[2]) / 4.5f;
        float gy = (tr[3] * X + tr[4] * Y + tr[5]) / 4.5f;
        float ix = gx * 72.f + 71.5f;
        float iy = gy * 72.f + 71.5f;
        float x0 = floorf(ix), y0 = floorf(iy);
        float wx = ix - x0, wy = iy - y0;
        int xi = (int)x0, yi = (int)y0;
        float v00 = samp(img, py, px, yi, xi);
        float v01 = samp(img, py, px, yi, xi + 1);
        float v10 = samp(img, py, px, yi + 1, xi);
        float v11 = samp(img, py, px, yi + 1, xi + 1);
        float o = (1.f - wy) * ((1.f - wx) * v00 + wx * v01) + wy * ((1.f - wx) * v10 + wx * v11);
        outp[(size_t)n * 1024 + idx] = o;
    }
}

extern "C" void kernel_launch(void* const* d_in, const int* in_sizes, int n_in,
                              void* d_out, int out_size) {
    const float* img = (const float*)d_in[0];
    const float* w1 = (const float*)d_in[1];
    const float* w2 = (const float*)d_in[2];
    const float* w3 = (const float*)d_in[3];
    const float* pw = (const float*)d_in[4];  const float* pb = (const float*)d_in[5];
    const float* tw = (const float*)d_in[6];  const float* tb = (const float*)d_in[7];
    const float* shw = (const float*)d_in[8]; const float* shb = (const float*)d_in[9];
    const float* scw = (const float*)d_in[10]; const float* scb = (const float*)d_in[11];
    const float* tiw = (const float*)d_in[12]; const float* tib = (const float*)d_in[13];

    float* out = (float*)d_out;          // transformed: 9216*1*32*32 floats
    float* aff = out + 9216 * 1024;      // aff: 9216*2*3 floats

    k_conv1<<<dim3(6, 192), 128>>>(img, w1);
    k_redp<<<16 * 64, 256>>>(0, 64, S1);
    k_redf<<<1, 64>>>(0, 16, 64, S1);
    k_conv2<<<dim3(12, 48), 128>>>(w2);
    k_redp<<<32 * 32, 256>>>(1, 32, S2);
    k_redf<<<1, 64>>>(1, 32, 32, S2);
    k_conv3<<<dim3(12, 24), 128>>>(w3);
    k_redp<<<64 * 16, 256>>>(2, 16, S3);
    k_redf<<<1, 64>>>(2, 64, 16, S3);
    k_heads<<<72, 128>>>(pw, pb, tw, tb, shw, shb, scw, scb, tiw, tib);
    k_transform<<<36, 256>>>(aff);
    k_sample<<<NPOS, 256>>>(img, out);
}

// round 3
// speedup vs baseline: 1.2442x; 1.0792x over previous
#include <cuda_runtime.h>
#include <math.h>

#define S1 589824   // 768*768
#define S2 147456   // 384*384
#define S3 36864    // 192*192
#define NPOS 9216   // 96*96

__device__ float  g_f1[16 * S1];
__device__ float  g_f2[32 * S2];
__device__ float  g_f3[64 * S3];
__device__ double2 g_part[1024];
__device__ float  g_mean[3][64];
__device__ float  g_rstd[3][64];
__device__ float  g_heads[6][NPOS];
__device__ float  g_tr[NPOS * 6];

// ---- packed f32x2 helpers (sm_100a FFMA2) ----
__device__ __forceinline__ unsigned long long pk2(float lo, float hi) {
    unsigned long long r;
    asm("mov.b64 %0, {%1, %2};" : "=l"(r) : "f"(lo), "f"(hi));
    return r;
}
__device__ __forceinline__ void fma2(unsigned long long& acc, unsigned long long a, unsigned long long b) {
    asm("fma.rn.f32x2 %0, %1, %2, %3;" : "=l"(acc) : "l"(a), "l"(b), "l"(acc));
}
__device__ __forceinline__ float2 unpk(unsigned long long v) {
    float2 f;
    asm("mov.b64 {%0, %1}, %2;" : "=f"(f.x), "=f"(f.y) : "l"(v));
    return f;
}

// ---------------- conv1: 1 -> 16, 3x3, s1, p1, raw output; FFMA2 over oc pairs ----------------
__global__ void __launch_bounds__(128) k_conv1(const float* __restrict__ img, const float* __restrict__ w) {
    __shared__ float2 sW2[8 * 9];   // [pair][k]
    int tid = threadIdx.x;
    if (tid < 72) {
        int pr = tid / 9, k = tid % 9;
        sW2[tid] = make_float2(w[(2 * pr) * 9 + k], w[(2 * pr + 1) * 9 + k]);
    }
    __syncthreads();
    int xg = tid & 31, y = tid >> 5;
    int x0 = blockIdx.x * 128 + 4 * xg;
    int yy = blockIdx.y * 4 + y;
    unsigned long long acc[32];
#pragma unroll
    for (int i = 0; i < 32; i++) acc[i] = 0ull;
#pragma unroll
    for (int ky = 0; ky < 3; ky++) {
        int gy = yy + ky - 1;
        float v[6];
        if (gy >= 0 && gy < 768) {
            float4 a = *(const float4*)&img[gy * 768 + x0];
            v[1] = a.x; v[2] = a.y; v[3] = a.z; v[4] = a.w;
            v[0] = (x0 - 1 >= 0) ? img[gy * 768 + x0 - 1] : 0.f;
            v[5] = (x0 + 4 < 768) ? img[gy * 768 + x0 + 4] : 0.f;
        } else {
#pragma unroll
            for (int c = 0; c < 6; c++) v[c] = 0.f;
        }
        unsigned long long pk[6];
#pragma unroll
        for (int j = 0; j < 6; j++) pk[j] = pk2(v[j], v[j]);
#pragma unroll
        for (int p = 0; p < 8; p++) {
            float2 w0 = sW2[p * 9 + ky * 3 + 0];
            float2 w1 = sW2[p * 9 + ky * 3 + 1];
            float2 w2 = sW2[p * 9 + ky * 3 + 2];
            unsigned long long W0 = pk2(w0.x, w0.y), W1 = pk2(w1.x, w1.y), W2 = pk2(w2.x, w2.y);
#pragma unroll
            for (int px = 0; px < 4; px++) {
                fma2(acc[p * 4 + px], pk[px], W0);
                fma2(acc[p * 4 + px], pk[px + 1], W1);
                fma2(acc[p * 4 + px], pk[px + 2], W2);
            }
        }
    }
#pragma unroll
    for (int p = 0; p < 8; p++) {
        float2 u0 = unpk(acc[p * 4 + 0]), u1 = unpk(acc[p * 4 + 1]);
        float2 u2 = unpk(acc[p * 4 + 2]), u3 = unpk(acc[p * 4 + 3]);
        int oc0 = 2 * p;
        *(float4*)&g_f1[oc0 * S1 + yy * 768 + x0] = make_float4(u0.x, u1.x, u2.x, u3.x);
        *(float4*)&g_f1[(oc0 + 1) * S1 + yy * 768 + x0] = make_float4(u0.y, u1.y, u2.y, u3.y);
    }
}

// ---------------- deterministic per-channel mean/var reduction ----------------
__global__ void k_redp(int stage, int P, int elems) {
    const float* src = (stage == 0) ? g_f1 : ((stage == 1) ? g_f2 : g_f3);
    int ch = blockIdx.x / P, p = blockIdx.x % P;
    int chunk = elems / P;
    const float* b = src + (size_t)ch * elems + (size_t)p * chunk;
    double s = 0.0, q = 0.0;
    for (int i = threadIdx.x * 4; i < chunk; i += 1024) {
        float4 v = *(const float4*)&b[i];
        s += (double)v.x; q = fma((double)v.x, (double)v.x, q);
        s += (double)v.y; q = fma((double)v.y, (double)v.y, q);
        s += (double)v.z; q = fma((double)v.z, (double)v.z, q);
        s += (double)v.w; q = fma((double)v.w, (double)v.w, q);
    }
    __shared__ double ss[256], sq[256];
    ss[threadIdx.x] = s; sq[threadIdx.x] = q;
    __syncthreads();
    for (int o = 128; o > 0; o >>= 1) {
        if (threadIdx.x < o) {
            ss[threadIdx.x] += ss[threadIdx.x + o];
            sq[threadIdx.x] += sq[threadIdx.x + o];
        }
        __syncthreads();
    }
    if (threadIdx.x == 0) { g_part[blockIdx.x].x = ss[0]; g_part[blockIdx.x].y = sq[0]; }
}

__global__ void k_redf(int stage, int C, int P, int elems) {
    int c = threadIdx.x;
    if (c >= C) return;
    double s = 0.0, q = 0.0;
    for (int p = 0; p < P; p++) { s += g_part[c * P + p].x; q += g_part[c * P + p].y; }
    double m = s / (double)elems;
    double var = q / (double)elems - m * m;
    g_mean[stage][c] = (float)m;
    g_rstd[stage][c] = (float)(1.0 / sqrt(var + 1e-5));
}

// ---------------- conv2: 16 -> 32, 3x3, s2, p1, bn_relu fused on input, FFMA2 ----------------
// block 128 = xg(8) x y(8) x ocg(2); tile 32x8; thread: 4px x 8 oc-pairs
__device__ __forceinline__ void fill2(float* buf, const float* src, int iy0, int ix0, float m, float rs,
                                      int warp, int lane) {
    for (int r = warp; r < 17; r += 4) {
        int gy = iy0 + r;
        bool rowok = (gy >= 0 && gy < 768);
        const float* srow = src + gy * 768;
        for (int c = lane; c < 65; c += 32) {
            int gx = ix0 + c;
            float v = 0.f;
            if (rowok && gx >= 0 && gx < 768) {
                v = (srow[gx] - m) * rs;
                v = v > 0.f ? v : 0.f;
            }
            buf[r * 68 + c] = v;
        }
    }
}

__global__ void __launch_bounds__(128) k_conv2(const float* __restrict__ w) {
    __shared__ float2 sW2[16 * 16 * 9];   // [ic][pair][k]
    __shared__ float  sIn[2][17 * 68];
    int tid = threadIdx.x;
    for (int i = tid; i < 2304; i += 128) {
        int ic = i / 144, r = i % 144, pr = r / 9, k = r % 9;
        int oc0 = 2 * pr;
        sW2[i] = make_float2(w[(oc0 * 16 + ic) * 9 + k], w[((oc0 + 1) * 16 + ic) * 9 + k]);
    }
    int xg = tid & 7, y = (tid >> 3) & 7, ocg = tid >> 6;
    int warp = tid >> 5, lane = tid & 31;
    int ox0 = blockIdx.x * 32, oy0 = blockIdx.y * 8;
    int ix0 = 2 * ox0 - 1, iy0 = 2 * oy0 - 1;
    fill2(sIn[0], g_f1, iy0, ix0, g_mean[0][0], g_rstd[0][0], warp, lane);
    __syncthreads();
    unsigned long long acc[32];
#pragma unroll
    for (int i = 0; i < 32; i++) acc[i] = 0ull;
    int r0 = 2 * y, c0 = 8 * xg;
#pragma unroll 1
    for (int ic = 0; ic < 16; ic++) {
        int cur = ic & 1;
        if (ic < 15)
            fill2(sIn[cur ^ 1], g_f1 + (size_t)(ic + 1) * S1, iy0, ix0,
                  g_mean[0][ic + 1], g_rstd[0][ic + 1], warp, lane);
        const float* buf = sIn[cur];
        const float2* wbase = &sW2[(ic * 16 + ocg * 8) * 9];
#pragma unroll
        for (int ky = 0; ky < 3; ky++) {
            const float* row = &buf[(r0 + ky) * 68 + c0];
            float4 a = *(const float4*)row;
            float4 b = *(const float4*)(row + 4);
            float v8 = row[8];
            unsigned long long pk[9];
            pk[0] = pk2(a.x, a.x); pk[1] = pk2(a.y, a.y); pk[2] = pk2(a.z, a.z);
            pk[3] = pk2(a.w, a.w); pk[4] = pk2(b.x, b.x); pk[5] = pk2(b.y, b.y);
            pk[6] = pk2(b.z, b.z); pk[7] = pk2(b.w, b.w); pk[8] = pk2(v8, v8);
#pragma unroll
            for (int p = 0; p < 8; p++) {
                float2 w0 = wbase[p * 9 + ky * 3 + 0];
                float2 w1 = wbase[p * 9 + ky * 3 + 1];
                float2 w2 = wbase[p * 9 + ky * 3 + 2];
                unsigned long long W0 = pk2(w0.x, w0.y), W1 = pk2(w1.x, w1.y), W2 = pk2(w2.x, w2.y);
#pragma unroll
                for (int px = 0; px < 4; px++) {
                    fma2(acc[p * 4 + px], pk[2 * px + 0], W0);
                    fma2(acc[p * 4 + px], pk[2 * px + 1], W1);
                    fma2(acc[p * 4 + px], pk[2 * px + 2], W2);
                }
            }
        }
        __syncthreads();
    }
    int oy = oy0 + y, oxb = ox0 + 4 * xg;
#pragma unroll
    for (int p = 0; p < 8; p++) {
        float2 u0 = unpk(acc[p * 4 + 0]), u1 = unpk(acc[p * 4 + 1]);
        float2 u2 = unpk(acc[p * 4 + 2]), u3 = unpk(acc[p * 4 + 3]);
        int oc0 = ocg * 16 + 2 * p;
        *(float4*)&g_f2[oc0 * S2 + oy * 384 + oxb] = make_float4(u0.x, u1.x, u2.x, u3.x);
        *(float4*)&g_f2[(oc0 + 1) * S2 + oy * 384 + oxb] = make_float4(u0.y, u1.y, u2.y, u3.y);
    }
}

// ---------------- conv3: 32 -> 64, 3x3, s2, p1, FFMA2, split over oc halves ----------------
// block 128 = xg(4) x y(8) x ocg(4); tile 16x8; thread: 4px x 4 oc-pairs; z = oc half
__device__ __forceinline__ void fill3(float* buf, const float* src, int iy0, int ix0, float m, float rs,
                                      int warp, int lane) {
    for (int r = warp; r < 17; r += 4) {
        int gy = iy0 + r;
        bool rowok = (gy >= 0 && gy < 384);
        const float* srow = src + gy * 384;
        for (int c = lane; c < 33; c += 32) {
            int gx = ix0 + c;
            float v = 0.f;
            if (rowok && gx >= 0 && gx < 384) {
                v = (srow[gx] - m) * rs;
                v = v > 0.f ? v : 0.f;
            }
            buf[r * 36 + c] = v;
        }
    }
}

__global__ void __launch_bounds__(128) k_conv3(const float* __restrict__ w) {
    __shared__ float2 sW2[32 * 16 * 9];   // [ic][pair-in-half][k]  36.9KB
    __shared__ float  sIn[2][17 * 36];
    int tid = threadIdx.x;
    int z = blockIdx.z;
    for (int i = tid; i < 4608; i += 128) {
        int ic = i / 144, r = i % 144, pr = r / 9, k = r % 9;
        int oc0 = z * 32 + 2 * pr;
        sW2[i] = make_float2(w[(oc0 * 32 + ic) * 9 + k], w[((oc0 + 1) * 32 + ic) * 9 + k]);
    }
    int xg = tid & 3, y = (tid >> 2) & 7, ocg = (tid >> 5) & 3;
    int warp = tid >> 5, lane = tid & 31;
    int ox0 = blockIdx.x * 16, oy0 = blockIdx.y * 8;
    int ix0 = 2 * ox0 - 1, iy0 = 2 * oy0 - 1;
    fill3(sIn[0], g_f2, iy0, ix0, g_mean[1][0], g_rstd[1][0], warp, lane);
    __syncthreads();
    unsigned long long acc[16];
#pragma unroll
    for (int i = 0; i < 16; i++) acc[i] = 0ull;
    int r0 = 2 * y, c0 = 8 * xg;
#pragma unroll 1
    for (int ic = 0; ic < 32; ic++) {
        int cur = ic & 1;
        if (ic < 31)
            fill3(sIn[cur ^ 1], g_f2 + (size_t)(ic + 1) * S2, iy0, ix0,
                  g_mean[1][ic + 1], g_rstd[1][ic + 1], warp, lane);
        const float* buf = sIn[cur];
        const float2* wbase = &sW2[(ic * 16 + ocg * 4) * 9];
#pragma unroll
        for (int ky = 0; ky < 3; ky++) {
            const float* row = &buf[(r0 + ky) * 36 + c0];
            float4 a = *(const float4*)row;
            float4 b = *(const float4*)(row + 4);
            float v8 = row[8];
            unsigned long long pk[9];
            pk[0] = pk2(a.x, a.x); pk[1] = pk2(a.y, a.y); pk[2] = pk2(a.z, a.z);
            pk[3] = pk2(a.w, a.w); pk[4] = pk2(b.x, b.x); pk[5] = pk2(b.y, b.y);
            pk[6] = pk2(b.z, b.z); pk[7] = pk2(b.w, b.w); pk[8] = pk2(v8, v8);
#pragma unroll
            for (int p = 0; p < 4; p++) {
                float2 w0 = wbase[p * 9 + ky * 3 + 0];
                float2 w1 = wbase[p * 9 + ky * 3 + 1];
                float2 w2 = wbase[p * 9 + ky * 3 + 2];
                unsigned long long W0 = pk2(w0.x, w0.y), W1 = pk2(w1.x, w1.y), W2 = pk2(w2.x, w2.y);
#pragma unroll
                for (int px = 0; px < 4; px++) {
                    fma2(acc[p * 4 + px], pk[2 * px + 0], W0);
                    fma2(acc[p * 4 + px], pk[2 * px + 1], W1);
                    fma2(acc[p * 4 + px], pk[2 * px + 2], W2);
                }
            }
        }
        __syncthreads();
    }
    int oy = oy0 + y, oxb = ox0 + 4 * xg;
#pragma unroll
    for (int p = 0; p < 4; p++) {
        float2 u0 = unpk(acc[p * 4 + 0]), u1 = unpk(acc[p * 4 + 1]);
        float2 u2 = unpk(acc[p * 4 + 2]), u3 = unpk(acc[p * 4 + 3]);
        int oc0 = z * 32 + ocg * 8 + 2 * p;
        *(float4*)&g_f3[oc0 * S3 + oy * 192 + oxb] = make_float4(u0.x, u1.x, u2.x, u3.x);
        *(float4*)&g_f3[(oc0 + 1) * S3 + oy * 192 + oxb] = make_float4(u0.y, u1.y, u2.y, u3.y);
    }
}

// ---------------- heads ----------------
__global__ void k_heads(const float* __restrict__ pw, const float* __restrict__ pb,
                        const float* __restrict__ tw, const float* __restrict__ tb,
                        const float* __restrict__ shw, const float* __restrict__ shb,
                        const float* __restrict__ scw, const float* __restrict__ scb,
                        const float* __restrict__ tiw, const float* __restrict__ tib) {
    __shared__ float sw[1536];
    __shared__ float sb[6];
    int tid = threadIdx.x;
    for (int i = tid; i < 1536; i += 128) {
        int h = i / 256, r = i % 256;
        const float* s; int off = r;
        if (h == 0) s = pw;
        else if (h == 1) s = tw;
        else if (h == 2) s = shw;
        else if (h == 3) { s = shw; off = r + 256; }
        else if (h == 4) s = scw;
        else s = tiw;
        sw[i] = s[off];
    }
    if (tid == 0) { sb[0] = pb[0]; sb[1] = tb[0]; sb[2] = shb[0]; sb[3] = shb[1]; sb[4] = scb[0]; sb[5] = tib[0]; }
    __syncthreads();
    int n = blockIdx.x * 128 + tid;
    int y = n / 96, x = n % 96;
    float acc[6] = {0.f, 0.f, 0.f, 0.f, 0.f, 0.f};
    for (int ic = 0; ic < 64; ic++) {
        float m = g_mean[2][ic], rs = g_rstd[2][ic];
        int base = ic * S3 + (2 * y) * 192 + 2 * x;
        float v0 = (g_f3[base] - m) * rs;       v0 = v0 > 0.f ? v0 : 0.f;
        float v1 = (g_f3[base + 1] - m) * rs;   v1 = v1 > 0.f ? v1 : 0.f;
        float v2 = (g_f3[base + 192] - m) * rs; v2 = v2 > 0.f ? v2 : 0.f;
        float v3 = (g_f3[base + 193] - m) * rs; v3 = v3 > 0.f ? v3 : 0.f;
#pragma unroll
        for (int h = 0; h < 6; h++) {
            const float* ww = &sw[h * 256 + ic * 4];
            acc[h] += v0 * ww[0] + v1 * ww[1] + v2 * ww[2] + v3 * ww[3];
        }
    }
    g_heads[0][n] = 3.14159f * tanhf(acc[0] + sb[0]);
    g_heads[1][n] = 3.14159f * tanhf(acc[1] + sb[1]);
    g_heads[2][n] = 0.2f * tanhf(acc[2] + sb[2]);
    g_heads[3][n] = 0.2f * tanhf(acc[3] + sb[3]);
    float sc = 1.f + 0.25f * tanhf(acc[4] + sb[4]);
    g_heads[4][n] = fminf(fmaxf(sc, 0.8f), 1.25f);
    float ti = 1.f + 0.8f * tanhf(acc[5] + sb[5]);
    g_heads[5][n] = fminf(fmaxf(ti, 1.0f), 1.8f);
}

// ---------------- transform build + aff output ----------------
__global__ void k_transform(float* __restrict__ aff) {
    int n = blockIdx.x * 256 + threadIdx.x;
    if (n >= NPOS) return;
    float psi = g_heads[0][n], th = g_heads[1][n];
    const float* sf = &g_heads[2][0];
    float sx = sf[2 * n], sy = sf[2 * n + 1];
    float s = g_heads[4][n], t = g_heads[5][n];
    float cp = cosf(psi), sp = sinf(psi), ct = cosf(th), st = sinf(th);
    float a = t * ct, b = -t * st, c = st / t, d = ct / t;
    float A00 = s * (cp * a - sp * c), A01 = s * (cp * b - sp * d);
    float A10 = s * (sp * a + cp * c), A11 = s * (sp * b + cp * d);
    float* tr = &g_tr[n * 6];
    tr[0] = A00; tr[1] = A01; tr[2] = sx; tr[3] = A10; tr[4] = A11; tr[5] = sy;
    float* af = aff + (size_t)n * 6;
    af[0] = 32.f * A00; af[1] = 32.f * A01; af[2] = (float)(4 + 8 * (n % 96)) + 32.f * sx;
    af[3] = 32.f * A10; af[4] = 32.f * A11; af[5] = (float)(4 + 8 * (n / 96)) + 32.f * sy;
}

// ---------------- bilinear sampler ----------------
__device__ __forceinline__ float samp(const float* __restrict__ img, int py, int px, int yy, int xx) {
    if ((unsigned)xx >= 144u || (unsigned)yy >= 144u) return 0.f;
    int r = py * 8 + yy - 68, c = px * 8 + xx - 68;
    if ((unsigned)r >= 768u || (unsigned)c >= 768u) return 0.f;
    return img[r * 768 + c];
}

__global__ void k_sample(const float* __restrict__ img, float* __restrict__ outp) {
    int n = blockIdx.x;
    __shared__ float tr[6];
    if (threadIdx.x < 6) tr[threadIdx.x] = g_tr[n * 6 + threadIdx.x];
    __syncthreads();
    int px = n % 96, py = n / 96;
#pragma unroll
    for (int j = 0; j < 4; j++) {
        int idx = threadIdx.x + j * 256;
        int h = idx >> 5, w = idx & 31;
        float X = (w + 0.5f) * 0.0625f - 1.f;
        float Y = (h + 0.5f) * 0.0625f - 1.f;
        float gx = (tr[0] * X + tr[1] * Y + tr[2]) / 4.5f;
        float gy = (tr[3] * X + tr[4] * Y + tr[5]) / 4.5f;
        float ix = gx * 72.f + 71.5f;
        float iy = gy * 72.f + 71.5f;
        float x0 = floorf(ix), y0 = floorf(iy);
        float wx = ix - x0, wy = iy - y0;
        int xi = (int)x0, yi = (int)y0;
        float v00 = samp(img, py, px, yi, xi);
        float v01 = samp(img, py, px, yi, xi + 1);
        float v10 = samp(img, py, px, yi + 1, xi);
        float v11 = samp(img, py, px, yi + 1, xi + 1);
        float o = (1.f - wy) * ((1.f - wx) * v00 + wx * v01) + wy * ((1.f - wx) * v10 + wx * v11);
        outp[(size_t)n * 1024 + idx] = o;
    }
}

extern "C" void kernel_launch(void* const* d_in, const int* in_sizes, int n_in,
                              void* d_out, int out_size) {
    const float* img = (const float*)d_in[0];
    const float* w1 = (const float*)d_in[1];
    const float* w2 = (const float*)d_in[2];
    const float* w3 = (const float*)d_in[3];
    const float* pw = (const float*)d_in[4];  const float* pb = (const float*)d_in[5];
    const float* tw = (const float*)d_in[6];  const float* tb = (const float*)d_in[7];
    const float* shw = (const float*)d_in[8]; const float* shb = (const float*)d_in[9];
    const float* scw = (const float*)d_in[10]; const float* scb = (const float*)d_in[11];
    const float* tiw = (const float*)d_in[12]; const float* tib = (const float*)d_in[13];

    float* out = (float*)d_out;          // transformed: 9216*1*32*32 floats
    float* aff = out + 9216 * 1024;      // aff: 9216*2*3 floats

    k_conv1<<<dim3(6, 192), 128>>>(img, w1);
    k_redp<<<16 * 64, 256>>>(0, 64, S1);
    k_redf<<<1, 64>>>(0, 16, 64, S1);
    k_conv2<<<dim3(12, 48), 128>>>(w2);
    k_redp<<<32 * 32, 256>>>(1, 32, S2);
    k_redf<<<1, 64>>>(1, 32, 32, S2);
    k_conv3<<<dim3(12, 24, 2), 128>>>(w3);
    k_redp<<<64 * 16, 256>>>(2, 16, S3);
    k_redf<<<1, 64>>>(2, 64, 16, S3);
    k_heads<<<72, 128>>>(pw, pb, tw, tb, shw, shb, scw, scb, tiw, tib);
    k_transform<<<36, 256>>>(aff);
    k_sample<<<NPOS, 256>>>(img, out);
}